// round 1
// baseline (speedup 1.0000x reference)
#include <cuda_runtime.h>
#include <math.h>
#include <stdint.h>

#define BATCH 1024
#define SEQ   512
#define HID   128
#define G3    384   // 3*HID

// h_seq scratch: 1024*512*128 floats = 256MB (static device array: allocation-free)
__device__ float g_hseq[(size_t)BATCH * SEQ * HID];

// ---------------------------------------------------------------------------
// Kernel 1: GRU recurrence. grid=128 CTAs, 256 threads, 8 batch rows per CTA.
// Shared: W_hh transposed [k][row] (192KB) + h double buffer [2][8][128].
// Thread j (=tid&127) computes gate rows j, 128+j, 256+j for 4 batches
// (half = tid>>7 selects batches 0-3 or 4-7 of the CTA's 8).
// ---------------------------------------------------------------------------
__global__ __launch_bounds__(256, 1) void gru_kernel(
    const float* __restrict__ v_seq,   // [B,S,2]
    const float* __restrict__ W_ih,    // [384,2]
    const float* __restrict__ W_hh,    // [384,128]
    const float* __restrict__ b_ih,    // [384]
    const float* __restrict__ b_hh)    // [384]
{
    extern __shared__ float smem[];
    float* W_sh = smem;                 // [128][384]: index k*384 + row
    float* h_sh = smem + HID * G3;      // [2][8][128]

    const int tid  = threadIdx.x;
    const int j    = tid & 127;
    const int half = tid >> 7;          // 0 or 1
    const int base = blockIdx.x * 8 + half * 4;   // first global batch of this half
    const int lb0  = half * 4;                    // first local batch (0 or 4)

    // Load + transpose W_hh into shared
    for (int idx = tid; idx < G3 * HID; idx += 256) {
        int row = idx >> 7;
        int k   = idx & 127;
        W_sh[k * G3 + row] = W_hh[idx];
    }
    // Zero h buffer 0
    for (int idx = tid; idx < 8 * HID; idx += 256) h_sh[idx] = 0.0f;

    // Per-thread constants (input projection rows + biases for rows j,128+j,256+j)
    const float wr0 = W_ih[2 * j],             wr1 = W_ih[2 * j + 1];
    const float wz0 = W_ih[2 * (HID + j)],     wz1 = W_ih[2 * (HID + j) + 1];
    const float wn0 = W_ih[2 * (2 * HID + j)], wn1 = W_ih[2 * (2 * HID + j) + 1];
    const float bir = b_ih[j], biz = b_ih[HID + j], bin_ = b_ih[2 * HID + j];
    const float bhr = b_hh[j], bhz = b_hh[HID + j], bhn  = b_hh[2 * HID + j];

    __syncthreads();

    for (int s = 0; s < SEQ; ++s) {
        const float* hc = h_sh + (s & 1) * (8 * HID);
        float* hn_buf   = h_sh + ((s & 1) ^ 1) * (8 * HID);

        float ar[4], az[4], an[4];
#pragma unroll
        for (int i = 0; i < 4; i++) { ar[i] = bhr; az[i] = bhz; an[i] = bhn; }

        // Main matvec: gh[row] += sum_k W_hh[row][k] * h[b][k], 4 batches
#pragma unroll 4
        for (int k = 0; k < HID; k += 4) {
            float wrk[4], wzk[4], wnk[4];
#pragma unroll
            for (int u = 0; u < 4; u++) {
                const float* wp = W_sh + (k + u) * G3;
                wrk[u] = wp[j];
                wzk[u] = wp[128 + j];
                wnk[u] = wp[256 + j];
            }
#pragma unroll
            for (int i = 0; i < 4; i++) {
                float4 hv = *(const float4*)(hc + (lb0 + i) * HID + k);
                ar[i] = fmaf(wrk[0], hv.x, ar[i]);
                ar[i] = fmaf(wrk[1], hv.y, ar[i]);
                ar[i] = fmaf(wrk[2], hv.z, ar[i]);
                ar[i] = fmaf(wrk[3], hv.w, ar[i]);
                az[i] = fmaf(wzk[0], hv.x, az[i]);
                az[i] = fmaf(wzk[1], hv.y, az[i]);
                az[i] = fmaf(wzk[2], hv.z, az[i]);
                az[i] = fmaf(wzk[3], hv.w, az[i]);
                an[i] = fmaf(wnk[0], hv.x, an[i]);
                an[i] = fmaf(wnk[1], hv.y, an[i]);
                an[i] = fmaf(wnk[2], hv.z, an[i]);
                an[i] = fmaf(wnk[3], hv.w, an[i]);
            }
        }

        // Gates + state update + h_seq store
#pragma unroll
        for (int i = 0; i < 4; i++) {
            const int gb = base + i;
            float2 vv = *(const float2*)(v_seq + ((size_t)gb * SEQ + s) * 2);
            float xr = fmaf(wr0, vv.x, fmaf(wr1, vv.y, bir));
            float xz = fmaf(wz0, vv.x, fmaf(wz1, vv.y, biz));
            float xn = fmaf(wn0, vv.x, fmaf(wn1, vv.y, bin_));
            float r = 1.0f / (1.0f + __expf(-(xr + ar[i])));
            float z = 1.0f / (1.0f + __expf(-(xz + az[i])));
            float n = tanhf(xn + r * an[i]);
            float hold = hc[(lb0 + i) * HID + j];
            float hnew = n + z * (hold - n);   // (1-z)*n + z*h
            hn_buf[(lb0 + i) * HID + j] = hnew;
            g_hseq[((size_t)gb * SEQ + s) * HID + j] = hnew;
        }
        __syncthreads();
    }
}

// ---------------------------------------------------------------------------
// Kernel 2: epilogue. One warp per (b,s): x_pred, x_prev, residual MLP,
// physics violations. Fully parallel.
// ---------------------------------------------------------------------------
__global__ __launch_bounds__(256) void epi_kernel(
    const float* __restrict__ x0,      // [B,2]
    const float* __restrict__ v_seq,   // [B,S,2]
    const float* __restrict__ W_out,   // [2,128]
    const float* __restrict__ b_out,   // [2]
    const float* __restrict__ W_r1,    // [64,4]
    const float* __restrict__ b_r1,    // [64]
    const float* __restrict__ W_r2,    // [2,64]
    const float* __restrict__ b_r2,    // [2]
    float* __restrict__ out)           // [2, B, S, 2]: x_pred then violations
{
    const int w    = (blockIdx.x * blockDim.x + threadIdx.x) >> 5;
    const int lane = threadIdx.x & 31;
    if (w >= BATCH * SEQ) return;
    const int b = w >> 9;       // SEQ = 512
    const int s = w & 511;

    const float4 w0 = *(const float4*)(W_out + lane * 4);
    const float4 w1 = *(const float4*)(W_out + HID + lane * 4);

    // x_pred at (b,s)
    const float* hp = g_hseq + ((size_t)b * SEQ + s) * HID;
    float4 hv = *(const float4*)(hp + lane * 4);
    float xp0 = hv.x * w0.x + hv.y * w0.y + hv.z * w0.z + hv.w * w0.w;
    float xp1 = hv.x * w1.x + hv.y * w1.y + hv.z * w1.z + hv.w * w1.w;
#pragma unroll
    for (int o = 16; o; o >>= 1) {
        xp0 += __shfl_xor_sync(0xffffffffu, xp0, o);
        xp1 += __shfl_xor_sync(0xffffffffu, xp1, o);
    }
    xp0 += b_out[0];
    xp1 += b_out[1];

    // x_prev: x0 at s==0, else x_pred at s-1 (recomputed from h_{s-1})
    float xq0, xq1;
    if (s == 0) {
        xq0 = x0[b * 2];
        xq1 = x0[b * 2 + 1];
    } else {
        float4 hu = *(const float4*)(hp - HID + lane * 4);
        xq0 = hu.x * w0.x + hu.y * w0.y + hu.z * w0.z + hu.w * w0.w;
        xq1 = hu.x * w1.x + hu.y * w1.y + hu.z * w1.z + hu.w * w1.w;
#pragma unroll
        for (int o = 16; o; o >>= 1) {
            xq0 += __shfl_xor_sync(0xffffffffu, xq0, o);
            xq1 += __shfl_xor_sync(0xffffffffu, xq1, o);
        }
        xq0 += b_out[0];
        xq1 += b_out[1];
    }

    float2 vv = *(const float2*)(v_seq + ((size_t)b * SEQ + s) * 2);

    // Residual MLP: ri = [xq0, xq1, v0, v1]; hid = relu(W_r1 @ ri + b_r1) (64);
    // res = W_r2 @ hid + b_r2. Each lane owns hidden units lane and lane+32.
    float r0p = 0.0f, r1p = 0.0f;
#pragma unroll
    for (int t = 0; t < 2; t++) {
        int m = lane + t * 32;
        float4 wr = *(const float4*)(W_r1 + m * 4);
        float hid = fmaf(wr.x, xq0, fmaf(wr.y, xq1, fmaf(wr.z, vv.x, fmaf(wr.w, vv.y, b_r1[m]))));
        hid = fmaxf(hid, 0.0f);
        r0p = fmaf(hid, W_r2[m], r0p);
        r1p = fmaf(hid, W_r2[64 + m], r1p);
    }
#pragma unroll
    for (int o = 16; o; o >>= 1) {
        r0p += __shfl_xor_sync(0xffffffffu, r0p, o);
        r1p += __shfl_xor_sync(0xffffffffu, r1p, o);
    }
    r0p += b_r2[0];
    r1p += b_r2[1];

    if (lane == 0) {
        float pp0 = xq0 + vv.x + r0p;
        float pp1 = xq1 + vv.y + r1p;
        size_t o = ((size_t)b * SEQ + s) * 2;
        out[o]     = xp0;
        out[o + 1] = xp1;
        out[(size_t)BATCH * SEQ * 2 + o]     = xp0 - pp0;
        out[(size_t)BATCH * SEQ * 2 + o + 1] = xp1 - pp1;
    }
}

// ---------------------------------------------------------------------------
extern "C" void kernel_launch(void* const* d_in, const int* in_sizes, int n_in,
                              void* d_out, int out_size)
{
    const float* x0    = (const float*)d_in[0];
    const float* v_seq = (const float*)d_in[1];
    const float* W_ih  = (const float*)d_in[2];
    const float* W_hh  = (const float*)d_in[3];
    const float* b_ih  = (const float*)d_in[4];
    const float* b_hh  = (const float*)d_in[5];
    const float* W_out = (const float*)d_in[6];
    const float* b_out = (const float*)d_in[7];
    const float* W_r1  = (const float*)d_in[8];
    const float* b_r1  = (const float*)d_in[9];
    const float* W_r2  = (const float*)d_in[10];
    const float* b_r2  = (const float*)d_in[11];
    float* out = (float*)d_out;

    const int smem_bytes = (HID * G3 + 2 * 8 * HID) * sizeof(float); // 204800
    cudaFuncSetAttribute(gru_kernel, cudaFuncAttributeMaxDynamicSharedMemorySize, smem_bytes);

    gru_kernel<<<BATCH / 8, 256, smem_bytes>>>(v_seq, W_ih, W_hh, b_ih, b_hh);

    const int total_warps = BATCH * SEQ;                 // one warp per (b,s)
    const int threads = 256;                             // 8 warps/block
    const int blocks = (total_warps * 32 + threads - 1) / threads;
    epi_kernel<<<blocks, threads>>>(x0, v_seq, W_out, b_out, W_r1, b_r1, W_r2, b_r2, out);
}

// round 2
// speedup vs baseline: 1.0762x; 1.0762x over previous
#include <cuda_runtime.h>
#include <math.h>
#include <stdint.h>

#define BATCH 1024
#define SEQ   512
#define HID   128
#define WPAD  130   // padded row stride (floats) for W_hh in smem: bank-balanced u64 loads

typedef unsigned long long u64;

// h_seq scratch: 1024*512*128 floats = 256MB (static device array: allocation-free)
__device__ float g_hseq[(size_t)BATCH * SEQ * HID];

// packed fp32x2 FMA: acc += a * b (lane-wise) — FFMA2 in SASS, 2 MACs/issue
#define FMA2(acc, a, b) asm("fma.rn.f32x2 %0, %1, %2, %0;" : "+l"(acc) : "l"(a), "l"(b))

__device__ __forceinline__ float f2sum(u64 v) {
    float lo, hi;
    asm("mov.b64 {%0, %1}, %2;" : "=f"(lo), "=f"(hi) : "l"(v));
    return lo + hi;
}

__device__ __forceinline__ float fast_sigmoid(float x) {
    float e = __expf(-x);
    return __fdividef(1.0f, 1.0f + e);
}
__device__ __forceinline__ float fast_tanh(float x) {
    // tanh(x) = 1 - 2/(e^{2x}+1); overflow-safe (e->inf => 1, e->0 => -1)
    float e = __expf(2.0f * x);
    return 1.0f - 2.0f * __fdividef(1.0f, e + 1.0f);
}

// ---------------------------------------------------------------------------
// GRU recurrence. 128 CTAs x 256 threads, 8 batch rows per CTA.
// Thread (j, kh): j = tid&127 owns gate rows j, 128+j, 256+j; kh = tid>>7
// covers k in [64*kh, 64*kh+64) for ALL 8 batches (k-split halves weight LDS
// traffic). Packed f32x2 accumulation along k. Partials for the "foreign"
// batch half are exchanged through smem; thread half kh applies gates to
// batches [4*kh, 4*kh+4).
// ---------------------------------------------------------------------------
__global__ __launch_bounds__(256, 1) void gru_kernel(
    const float* __restrict__ v_seq,   // [B,S,2]
    const float* __restrict__ W_ih,    // [384,2]
    const float* __restrict__ W_hh,    // [384,128]
    const float* __restrict__ b_ih,    // [384]
    const float* __restrict__ b_hh)    // [384]
{
    extern __shared__ float smem[];
    float* W_sh = smem;                       // [384][WPAD]
    float* h_sh = W_sh + 384 * WPAD;          // [2][8][128] double buffer
    float* p_sh = h_sh + 2 * 8 * HID;         // [24][128] partial sums

    const int tid   = threadIdx.x;
    const int j     = tid & 127;
    const int kh    = tid >> 7;         // k-half: 0 or 1
    const int kbase = kh * 64;
    const int ob0   = kh * 4;           // own batches (gates): ob0..ob0+3
    const int fb0   = 4 - ob0;          // foreign batches (partials written)
    const int bglob = blockIdx.x * 8;

    // Load W_hh into padded smem
    for (int idx = tid; idx < 384 * HID; idx += 256) {
        int row = idx >> 7, k = idx & 127;
        W_sh[row * WPAD + k] = W_hh[idx];
    }
    for (int idx = tid; idx < 8 * HID; idx += 256) h_sh[idx] = 0.0f;

    // Per-thread input-projection weights + biases (r,z biases merged)
    const float wr0 = W_ih[2 * j],               wr1 = W_ih[2 * j + 1];
    const float wz0 = W_ih[2 * (HID + j)],       wz1 = W_ih[2 * (HID + j) + 1];
    const float wn0 = W_ih[2 * (2 * HID + j)],   wn1 = W_ih[2 * (2 * HID + j) + 1];
    const float brt = b_ih[j] + b_hh[j];
    const float bzt = b_ih[HID + j] + b_hh[HID + j];
    const float bin_ = b_ih[2 * HID + j];
    const float bhn  = b_hh[2 * HID + j];

    __syncthreads();

    const float* Wr = W_sh + j * WPAD + kbase;
    const float* Wz = W_sh + (HID + j) * WPAD + kbase;
    const float* Wn = W_sh + (2 * HID + j) * WPAD + kbase;

    // v prefetch (own batches, step 0)
    float2 vv[4];
#pragma unroll
    for (int i = 0; i < 4; i++)
        vv[i] = *(const float2*)(v_seq + ((size_t)(bglob + ob0 + i) * SEQ) * 2);

    for (int s = 0; s < SEQ; ++s) {
        const float* hc = h_sh + (s & 1) * (8 * HID);
        float* hnb      = h_sh + ((s & 1) ^ 1) * (8 * HID);

        // prefetch next step's v (latency hidden behind the matvec)
        float2 vnx[4];
        int sn = (s + 1 < SEQ) ? (s + 1) : s;
#pragma unroll
        for (int i = 0; i < 4; i++)
            vnx[i] = *(const float2*)(v_seq + ((size_t)(bglob + ob0 + i) * SEQ + sn) * 2);

        u64 acc[8][3];
#pragma unroll
        for (int b = 0; b < 8; b++) { acc[b][0] = 0ull; acc[b][1] = 0ull; acc[b][2] = 0ull; }

        // matvec over this thread's k-half, packed 2 k's per FFMA2
#pragma unroll
        for (int k = 0; k < 64; k += 4) {
            u64 a0 = *(const u64*)(Wr + k), a1 = *(const u64*)(Wr + k + 2);
            u64 b0 = *(const u64*)(Wz + k), b1 = *(const u64*)(Wz + k + 2);
            u64 c0 = *(const u64*)(Wn + k), c1 = *(const u64*)(Wn + k + 2);
#pragma unroll
            for (int b = 0; b < 8; b++) {
                ulonglong2 h2 = *(const ulonglong2*)(hc + b * HID + kbase + k);
                FMA2(acc[b][0], a0, h2.x); FMA2(acc[b][0], a1, h2.y);
                FMA2(acc[b][1], b0, h2.x); FMA2(acc[b][1], b1, h2.y);
                FMA2(acc[b][2], c0, h2.x); FMA2(acc[b][2], c1, h2.y);
            }
        }

        // write partials for the foreign batch half
#pragma unroll
        for (int i = 0; i < 4; i++) {
            int b = fb0 + i;
            p_sh[(b * 3 + 0) * 128 + j] = f2sum(acc[b][0]);
            p_sh[(b * 3 + 1) * 128 + j] = f2sum(acc[b][1]);
            p_sh[(b * 3 + 2) * 128 + j] = f2sum(acc[b][2]);
        }
        __syncthreads();

        // gates for own batch half
#pragma unroll
        for (int i = 0; i < 4; i++) {
            int b = ob0 + i;
            float hr = f2sum(acc[b][0]) + p_sh[(b * 3 + 0) * 128 + j];
            float hz = f2sum(acc[b][1]) + p_sh[(b * 3 + 1) * 128 + j];
            float hn = f2sum(acc[b][2]) + p_sh[(b * 3 + 2) * 128 + j] + bhn;
            float r = fast_sigmoid(fmaf(wr0, vv[i].x, fmaf(wr1, vv[i].y, brt)) + hr);
            float z = fast_sigmoid(fmaf(wz0, vv[i].x, fmaf(wz1, vv[i].y, bzt)) + hz);
            float n = fast_tanh(fmaf(wn0, vv[i].x, fmaf(wn1, vv[i].y, bin_)) + r * hn);
            float hold = hc[b * HID + j];
            float hnew = n + z * (hold - n);
            hnb[b * HID + j] = hnew;
            g_hseq[((size_t)(bglob + b) * SEQ + s) * HID + j] = hnew;
        }
#pragma unroll
        for (int i = 0; i < 4; i++) vv[i] = vnx[i];
        __syncthreads();
    }
}

// ---------------------------------------------------------------------------
// Epilogue pass 1: x_pred only. One warp per (b,s); single h load per warp.
// ---------------------------------------------------------------------------
__global__ __launch_bounds__(256) void epi1_kernel(
    const float* __restrict__ W_out,   // [2,128]
    const float* __restrict__ b_out,   // [2]
    float* __restrict__ out)           // x_pred region: [B*S, 2]
{
    const int w    = (blockIdx.x * blockDim.x + threadIdx.x) >> 5;
    const int lane = threadIdx.x & 31;
    if (w >= BATCH * SEQ) return;

    const float4 w0 = *(const float4*)(W_out + lane * 4);
    const float4 w1 = *(const float4*)(W_out + HID + lane * 4);

    float4 hv = *(const float4*)(g_hseq + (size_t)w * HID + lane * 4);
    float xp0 = hv.x * w0.x + hv.y * w0.y + hv.z * w0.z + hv.w * w0.w;
    float xp1 = hv.x * w1.x + hv.y * w1.y + hv.z * w1.z + hv.w * w1.w;
#pragma unroll
    for (int o = 16; o; o >>= 1) {
        xp0 += __shfl_xor_sync(0xffffffffu, xp0, o);
        xp1 += __shfl_xor_sync(0xffffffffu, xp1, o);
    }
    if (lane == 0) {
        out[2 * (size_t)w]     = xp0 + b_out[0];
        out[2 * (size_t)w + 1] = xp1 + b_out[1];
    }
}

// ---------------------------------------------------------------------------
// Epilogue pass 2: violations. One thread per (b,s); x_prev read from pass 1
// output. MLP weights staged in smem (broadcast LDS).
// ---------------------------------------------------------------------------
__global__ __launch_bounds__(256) void epi2_kernel(
    const float* __restrict__ x0,      // [B,2]
    const float* __restrict__ v_seq,   // [B,S,2]
    const float* __restrict__ W_r1,    // [64,4]
    const float* __restrict__ b_r1,    // [64]
    const float* __restrict__ W_r2,    // [2,64]
    const float* __restrict__ b_r2,    // [2]
    float* __restrict__ out)           // [2, B*S, 2]
{
    __shared__ float4 s_w1[64];
    __shared__ float  s_b1[64], s_w2a[64], s_w2b[64], s_b2[2];
    const int t = threadIdx.x;
    if (t < 64) {
        s_w1[t]  = *(const float4*)(W_r1 + t * 4);
        s_b1[t]  = b_r1[t];
        s_w2a[t] = W_r2[t];
        s_w2b[t] = W_r2[64 + t];
    }
    if (t < 2) s_b2[t] = b_r2[t];
    __syncthreads();

    const int idx = blockIdx.x * blockDim.x + t;
    if (idx >= BATCH * SEQ) return;
    const int b = idx >> 9;
    const int s = idx & 511;

    float xq0, xq1;
    if (s == 0) {
        xq0 = x0[2 * b];
        xq1 = x0[2 * b + 1];
    } else {
        xq0 = out[2 * (size_t)(idx - 1)];
        xq1 = out[2 * (size_t)(idx - 1) + 1];
    }
    const float xp0 = out[2 * (size_t)idx];
    const float xp1 = out[2 * (size_t)idx + 1];
    const float2 vv = *(const float2*)(v_seq + (size_t)idx * 2);

    float r0 = 0.0f, r1 = 0.0f;
#pragma unroll 8
    for (int m = 0; m < 64; m++) {
        float4 wq = s_w1[m];
        float h = fmaf(wq.x, xq0, fmaf(wq.y, xq1, fmaf(wq.z, vv.x, fmaf(wq.w, vv.y, s_b1[m]))));
        h = fmaxf(h, 0.0f);
        r0 = fmaf(h, s_w2a[m], r0);
        r1 = fmaf(h, s_w2b[m], r1);
    }
    const float pp0 = xq0 + vv.x + r0 + s_b2[0];
    const float pp1 = xq1 + vv.y + r1 + s_b2[1];

    const size_t off = (size_t)BATCH * SEQ * 2;
    out[off + 2 * (size_t)idx]     = xp0 - pp0;
    out[off + 2 * (size_t)idx + 1] = xp1 - pp1;
}

// ---------------------------------------------------------------------------
extern "C" void kernel_launch(void* const* d_in, const int* in_sizes, int n_in,
                              void* d_out, int out_size)
{
    const float* x0    = (const float*)d_in[0];
    const float* v_seq = (const float*)d_in[1];
    const float* W_ih  = (const float*)d_in[2];
    const float* W_hh  = (const float*)d_in[3];
    const float* b_ih  = (const float*)d_in[4];
    const float* b_hh  = (const float*)d_in[5];
    const float* W_out = (const float*)d_in[6];
    const float* b_out = (const float*)d_in[7];
    const float* W_r1  = (const float*)d_in[8];
    const float* b_r1  = (const float*)d_in[9];
    const float* W_r2  = (const float*)d_in[10];
    const float* b_r2  = (const float*)d_in[11];
    float* out = (float*)d_out;

    const int smem_bytes = (384 * WPAD + 2 * 8 * HID + 24 * 128) * sizeof(float); // 220160
    cudaFuncSetAttribute(gru_kernel, cudaFuncAttributeMaxDynamicSharedMemorySize, smem_bytes);

    gru_kernel<<<BATCH / 8, 256, smem_bytes>>>(v_seq, W_ih, W_hh, b_ih, b_hh);

    // pass 1: x_pred (one warp per (b,s))
    {
        const int total = BATCH * SEQ * 32;
        epi1_kernel<<<(total + 255) / 256, 256>>>(W_out, b_out, out);
    }
    // pass 2: violations (one thread per (b,s))
    {
        const int total = BATCH * SEQ;
        epi2_kernel<<<(total + 255) / 256, 256>>>(x0, v_seq, W_r1, b_r1, W_r2, b_r2, out);
    }
}

// round 3
// speedup vs baseline: 1.4562x; 1.3531x over previous
#include <cuda_runtime.h>
#include <math.h>
#include <stdint.h>

#define BATCH 1024
#define SEQ   512
#define HID   128
#define G3    384

typedef unsigned long long u64;

// h_seq scratch: 1024*512*128 floats = 256MB (static device array: allocation-free)
__device__ float g_hseq[(size_t)BATCH * SEQ * HID];

// packed fp32x2 ops (FFMA2 / FADD2 in SASS)
#define FMA2(acc, a, b) asm("fma.rn.f32x2 %0, %1, %2, %0;" : "+l"(acc) : "l"(a), "l"(b))
#define ADD2(a, b)      asm("add.rn.f32x2 %0, %0, %1;" : "+l"(a) : "l"(b))

__device__ __forceinline__ u64 dupf(float w) {
    u64 d; asm("mov.b64 %0, {%1, %1};" : "=l"(d) : "f"(w)); return d;
}
__device__ __forceinline__ float2 unpk(u64 v) {
    float2 r; asm("mov.b64 {%0, %1}, %2;" : "=f"(r.x), "=f"(r.y) : "l"(v)); return r;
}
__device__ __forceinline__ float fast_sigmoid(float x) {
    float e = __expf(-x);
    return __fdividef(1.0f, 1.0f + e);
}
__device__ __forceinline__ float fast_tanh(float x) {
    float e = __expf(2.0f * x);
    return 1.0f - 2.0f * __fdividef(1.0f, e + 1.0f);
}

// ---------------------------------------------------------------------------
// GRU recurrence. 128 CTAs x 512 threads, 8 batch rows per CTA.
// Thread (j = tid&127, q = tid>>7): computes gate rows j, 128+j, 256+j over
// k in [32q, 32q+32) for all 8 batches. Accumulators are f32x2 packed along
// BATCH pairs; weights conflict-free LDS.32 from W_sh[k][row]; h broadcast
// LDS.128 from batch-interleaved h_il[k][b]. Two-stage k-partial reduction
// through 24KB smem; q==0 warps (one per SMSP) run the gate nonlinearity.
// ---------------------------------------------------------------------------
__global__ __launch_bounds__(512, 1) void gru_kernel(
    const float* __restrict__ v_seq,   // [B,S,2]
    const float* __restrict__ W_ih,    // [384,2]
    const float* __restrict__ W_hh,    // [384,128]
    const float* __restrict__ b_ih,    // [384]
    const float* __restrict__ b_hh)    // [384]
{
    extern __shared__ float smem[];
    float* W_sh = smem;                          // [128 k][384 row]
    float* h_il = smem + 128 * G3;               // [128 k][8 b]
    u64*   pA   = (u64*)(h_il + 128 * 8);        // [12][128]
    u64*   pB   = pA + 12 * 128;                 // [12][128]

    const int tid = threadIdx.x;
    const int j   = tid & 127;
    const int q   = tid >> 7;        // k-quarter 0..3
    const int bglob = blockIdx.x * 8;

    // Load W_hh transposed into [k][row]
    for (int idx = tid; idx < G3 * HID; idx += 512) {
        int row = idx >> 7, k = idx & 127;
        W_sh[k * G3 + row] = W_hh[idx];
    }
    for (int idx = tid; idx < 128 * 8; idx += 512) h_il[idx] = 0.0f;

    // Gate constants (only q==0 uses them)
    float wr0 = 0, wr1 = 0, wz0 = 0, wz1 = 0, wn0 = 0, wn1 = 0;
    float brt = 0, bzt = 0, bin_ = 0, bhn = 0;
    if (q == 0) {
        wr0 = W_ih[2 * j];                wr1 = W_ih[2 * j + 1];
        wz0 = W_ih[2 * (HID + j)];        wz1 = W_ih[2 * (HID + j) + 1];
        wn0 = W_ih[2 * (2 * HID + j)];    wn1 = W_ih[2 * (2 * HID + j) + 1];
        brt = b_ih[j] + b_hh[j];
        bzt = b_ih[HID + j] + b_hh[HID + j];
        bin_ = b_ih[2 * HID + j];
        bhn  = b_hh[2 * HID + j];
    }
    __syncthreads();

    const float* Wj0 = W_sh + j + (size_t)(q * 32) * G3;  // this quarter's first k row-col

    for (int s = 0; s < SEQ; ++s) {
        // prefetch v for gate phase (hidden behind the matvec)
        float2 vv[8];
        if (q == 0) {
#pragma unroll
            for (int b = 0; b < 8; b++)
                vv[b] = *(const float2*)(v_seq + ((size_t)(bglob + b) * SEQ + s) * 2);
        }

        u64 acc[3][4];   // [gate][batch-pair]
#pragma unroll
        for (int g = 0; g < 3; g++)
#pragma unroll
            for (int p = 0; p < 4; p++) acc[g][p] = 0ull;

        const float* Wk = Wj0;
        const float* hk = h_il + q * 32 * 8;

        // 16 groups of 2 k's
#pragma unroll
        for (int grp = 0; grp < 16; grp++) {
            float a0 = Wk[0],   b0 = Wk[128],       c0 = Wk[256];
            float a1 = Wk[G3],  b1 = Wk[G3 + 128],  c1 = Wk[G3 + 256];
            ulonglong2 hx0 = *(const ulonglong2*)(hk);        // k,   b0..3
            ulonglong2 hx1 = *(const ulonglong2*)(hk + 4);    // k,   b4..7
            ulonglong2 hy0 = *(const ulonglong2*)(hk + 8);    // k+1, b0..3
            ulonglong2 hy1 = *(const ulonglong2*)(hk + 12);   // k+1, b4..7
            u64 A0 = dupf(a0), B0 = dupf(b0), C0 = dupf(c0);
            u64 A1 = dupf(a1), B1 = dupf(b1), C1 = dupf(c1);

            FMA2(acc[0][0], A0, hx0.x); FMA2(acc[0][1], A0, hx0.y);
            FMA2(acc[0][2], A0, hx1.x); FMA2(acc[0][3], A0, hx1.y);
            FMA2(acc[1][0], B0, hx0.x); FMA2(acc[1][1], B0, hx0.y);
            FMA2(acc[1][2], B0, hx1.x); FMA2(acc[1][3], B0, hx1.y);
            FMA2(acc[2][0], C0, hx0.x); FMA2(acc[2][1], C0, hx0.y);
            FMA2(acc[2][2], C0, hx1.x); FMA2(acc[2][3], C0, hx1.y);

            FMA2(acc[0][0], A1, hy0.x); FMA2(acc[0][1], A1, hy0.y);
            FMA2(acc[0][2], A1, hy1.x); FMA2(acc[0][3], A1, hy1.y);
            FMA2(acc[1][0], B1, hy0.x); FMA2(acc[1][1], B1, hy0.y);
            FMA2(acc[1][2], B1, hy1.x); FMA2(acc[1][3], B1, hy1.y);
            FMA2(acc[2][0], C1, hy0.x); FMA2(acc[2][1], C1, hy0.y);
            FMA2(acc[2][2], C1, hy1.x); FMA2(acc[2][3], C1, hy1.y);

            Wk += 2 * G3;
            hk += 16;
        }

        u64* af = &acc[0][0];   // 12 flat accumulators

        // stage 0: q2 -> pA, q3 -> pB
        if (q == 2) {
#pragma unroll
            for (int i = 0; i < 12; i++) pA[i * 128 + j] = af[i];
        } else if (q == 3) {
#pragma unroll
            for (int i = 0; i < 12; i++) pB[i * 128 + j] = af[i];
        }
        __syncthreads();

        // stage 1: q0 += pA; q1 += pB then writes combined into its own pB slot
        if (q == 0) {
#pragma unroll
            for (int i = 0; i < 12; i++) ADD2(af[i], pA[i * 128 + j]);
        } else if (q == 1) {
#pragma unroll
            for (int i = 0; i < 12; i++) {
                ADD2(af[i], pB[i * 128 + j]);
                pB[i * 128 + j] = af[i];
            }
        }
        __syncthreads();

        // stage 2 + gates: q0 only (one warp per SMSP)
        if (q == 0) {
#pragma unroll
            for (int i = 0; i < 12; i++) ADD2(af[i], pB[i * 128 + j]);

            float hn8[8];
#pragma unroll
            for (int bp = 0; bp < 4; bp++) {
                float2 gr = unpk(acc[0][bp]);
                float2 gz = unpk(acc[1][bp]);
                float2 gn = unpk(acc[2][bp]);
#pragma unroll
                for (int e = 0; e < 2; e++) {
                    int b = 2 * bp + e;
                    float hr = e ? gr.y : gr.x;
                    float hz = e ? gz.y : gz.x;
                    float hn = e ? gn.y : gn.x;
                    float2 v = vv[b];
                    float r = fast_sigmoid(fmaf(wr0, v.x, fmaf(wr1, v.y, brt)) + hr);
                    float z = fast_sigmoid(fmaf(wz0, v.x, fmaf(wz1, v.y, bzt)) + hz);
                    float n = fast_tanh(fmaf(wn0, v.x, fmaf(wn1, v.y, bin_)) + r * (hn + bhn));
                    float hold = h_il[j * 8 + b];
                    hn8[b] = n + z * (hold - n);
                }
            }
            // write new h (batch-interleaved) + h_seq
            *(float4*)(h_il + j * 8)     = make_float4(hn8[0], hn8[1], hn8[2], hn8[3]);
            *(float4*)(h_il + j * 8 + 4) = make_float4(hn8[4], hn8[5], hn8[6], hn8[7]);
#pragma unroll
            for (int b = 0; b < 8; b++)
                g_hseq[((size_t)(bglob + b) * SEQ + s) * HID + j] = hn8[b];
        }
        __syncthreads();
    }
}

// ---------------------------------------------------------------------------
// Epilogue pass 1: x_pred only. One warp per (b,s).
// ---------------------------------------------------------------------------
__global__ __launch_bounds__(256) void epi1_kernel(
    const float* __restrict__ W_out,   // [2,128]
    const float* __restrict__ b_out,   // [2]
    float* __restrict__ out)           // x_pred region: [B*S, 2]
{
    const int w    = (blockIdx.x * blockDim.x + threadIdx.x) >> 5;
    const int lane = threadIdx.x & 31;
    if (w >= BATCH * SEQ) return;

    const float4 w0 = *(const float4*)(W_out + lane * 4);
    const float4 w1 = *(const float4*)(W_out + HID + lane * 4);

    float4 hv = *(const float4*)(g_hseq + (size_t)w * HID + lane * 4);
    float xp0 = hv.x * w0.x + hv.y * w0.y + hv.z * w0.z + hv.w * w0.w;
    float xp1 = hv.x * w1.x + hv.y * w1.y + hv.z * w1.z + hv.w * w1.w;
#pragma unroll
    for (int o = 16; o; o >>= 1) {
        xp0 += __shfl_xor_sync(0xffffffffu, xp0, o);
        xp1 += __shfl_xor_sync(0xffffffffu, xp1, o);
    }
    if (lane == 0) {
        out[2 * (size_t)w]     = xp0 + b_out[0];
        out[2 * (size_t)w + 1] = xp1 + b_out[1];
    }
}

// ---------------------------------------------------------------------------
// Epilogue pass 2: violations. One thread per (b,s).
// ---------------------------------------------------------------------------
__global__ __launch_bounds__(256) void epi2_kernel(
    const float* __restrict__ x0,      // [B,2]
    const float* __restrict__ v_seq,   // [B,S,2]
    const float* __restrict__ W_r1,    // [64,4]
    const float* __restrict__ b_r1,    // [64]
    const float* __restrict__ W_r2,    // [2,64]
    const float* __restrict__ b_r2,    // [2]
    float* __restrict__ out)           // [2, B*S, 2]
{
    __shared__ float4 s_w1[64];
    __shared__ float  s_b1[64], s_w2a[64], s_w2b[64], s_b2[2];
    const int t = threadIdx.x;
    if (t < 64) {
        s_w1[t]  = *(const float4*)(W_r1 + t * 4);
        s_b1[t]  = b_r1[t];
        s_w2a[t] = W_r2[t];
        s_w2b[t] = W_r2[64 + t];
    }
    if (t < 2) s_b2[t] = b_r2[t];
    __syncthreads();

    const int idx = blockIdx.x * blockDim.x + t;
    if (idx >= BATCH * SEQ) return;
    const int b = idx >> 9;
    const int s = idx & 511;

    float xq0, xq1;
    if (s == 0) {
        xq0 = x0[2 * b];
        xq1 = x0[2 * b + 1];
    } else {
        xq0 = out[2 * (size_t)(idx - 1)];
        xq1 = out[2 * (size_t)(idx - 1) + 1];
    }
    const float xp0 = out[2 * (size_t)idx];
    const float xp1 = out[2 * (size_t)idx + 1];
    const float2 vv = *(const float2*)(v_seq + (size_t)idx * 2);

    float r0 = 0.0f, r1 = 0.0f;
#pragma unroll 8
    for (int m = 0; m < 64; m++) {
        float4 wq = s_w1[m];
        float h = fmaf(wq.x, xq0, fmaf(wq.y, xq1, fmaf(wq.z, vv.x, fmaf(wq.w, vv.y, s_b1[m]))));
        h = fmaxf(h, 0.0f);
        r0 = fmaf(h, s_w2a[m], r0);
        r1 = fmaf(h, s_w2b[m], r1);
    }
    const float pp0 = xq0 + vv.x + r0 + s_b2[0];
    const float pp1 = xq1 + vv.y + r1 + s_b2[1];

    const size_t off = (size_t)BATCH * SEQ * 2;
    out[off + 2 * (size_t)idx]     = xp0 - pp0;
    out[off + 2 * (size_t)idx + 1] = xp1 - pp1;
}

// ---------------------------------------------------------------------------
extern "C" void kernel_launch(void* const* d_in, const int* in_sizes, int n_in,
                              void* d_out, int out_size)
{
    const float* x0    = (const float*)d_in[0];
    const float* v_seq = (const float*)d_in[1];
    const float* W_ih  = (const float*)d_in[2];
    const float* W_hh  = (const float*)d_in[3];
    const float* b_ih  = (const float*)d_in[4];
    const float* b_hh  = (const float*)d_in[5];
    const float* W_out = (const float*)d_in[6];
    const float* b_out = (const float*)d_in[7];
    const float* W_r1  = (const float*)d_in[8];
    const float* b_r1  = (const float*)d_in[9];
    const float* W_r2  = (const float*)d_in[10];
    const float* b_r2  = (const float*)d_in[11];
    float* out = (float*)d_out;

    // smem: W (192KB) + h_il (4KB) + 2 partial regions (24KB) = 225280 B
    const int smem_bytes = (128 * G3 + 128 * 8) * sizeof(float) + 2 * 12 * 128 * sizeof(u64);
    cudaFuncSetAttribute(gru_kernel, cudaFuncAttributeMaxDynamicSharedMemorySize, smem_bytes);

    gru_kernel<<<BATCH / 8, 512, smem_bytes>>>(v_seq, W_ih, W_hh, b_ih, b_hh);

    // pass 1: x_pred (one warp per (b,s))
    {
        const int total = BATCH * SEQ * 32;
        epi1_kernel<<<(total + 255) / 256, 256>>>(W_out, b_out, out);
    }
    // pass 2: violations (one thread per (b,s))
    {
        const int total = BATCH * SEQ;
        epi2_kernel<<<(total + 255) / 256, 256>>>(x0, v_seq, W_r1, b_r1, W_r2, b_r2, out);
    }
}

// round 5
// speedup vs baseline: 2.1616x; 1.4844x over previous
#include <cuda_runtime.h>
#include <cuda_bf16.h>
#include <math.h>
#include <stdint.h>

#define BATCH 1024
#define SEQ   512
#define HID   128
#define G3    384

typedef unsigned long long u64;
typedef unsigned short u16;

// h_seq scratch: 1024*512*128 floats = 256MB (static device array: allocation-free)
__device__ float g_hseq[(size_t)BATCH * SEQ * HID];

// ---------------- SMEM layout ----------------
// A_hi frags: [24 mt][8 kt][32 lane][4 u32]  = 98304 B  (W_hh hi split, mma-fragment order)
// A_lo frags: same                            = 98304 B
// hB_hi: [64 kpair][8 b] u32 (bf16x2 of k,k+1)=  2048 B
// hB_lo: same                                 =  2048 B
// Dbuf : [384 row][10 pad] f32                = 15360 B
#define OFF_A_HI  0
#define OFF_A_LO  98304
#define OFF_HB_HI 196608
#define OFF_HB_LO 198656
#define OFF_D     200704
#define SMEM_BYTES 216064

#define DSTRIDE 10

__device__ __forceinline__ void mma_bf16(float d[4], const uint4 a, uint32_t b0, uint32_t b1) {
    asm volatile(
        "mma.sync.aligned.m16n8k16.row.col.f32.bf16.bf16.f32 "
        "{%0,%1,%2,%3}, {%4,%5,%6,%7}, {%8,%9}, {%0,%1,%2,%3};"
        : "+f"(d[0]), "+f"(d[1]), "+f"(d[2]), "+f"(d[3])
        : "r"(a.x), "r"(a.y), "r"(a.z), "r"(a.w), "r"(b0), "r"(b1));
}

__device__ __forceinline__ void bsplit(float f, u16& hi, u16& lo) {
    __nv_bfloat16 h = __float2bfloat16(f);
    __nv_bfloat16 l = __float2bfloat16(f - __bfloat162float(h));
    hi = *(u16*)&h;
    lo = *(u16*)&l;
}

__device__ __forceinline__ float fast_sigmoid(float x) {
    float e = __expf(-x);
    return __fdividef(1.0f, 1.0f + e);
}
__device__ __forceinline__ float fast_tanh(float x) {
    float e = __expf(2.0f * x);
    return 1.0f - 2.0f * __fdividef(1.0f, e + 1.0f);
}

// ---------------------------------------------------------------------------
// GRU recurrence via mma.sync bf16-split. 128 CTAs x 768 threads (24 warps),
// 8 batches per CTA. Warp w owns M-tile w (rows 16w..16w+15 of the 384-row
// gate matrix). Each step: 24 HMMA/warp (8 k-tiles x 3 split products, fp32
// accum), D staged through padded smem, 512 gate threads apply nonlinearity
// (h_old in registers) and write h' bf16 hi/lo pairs back for the next step.
// ---------------------------------------------------------------------------
__global__ __launch_bounds__(768, 1) void gru_kernel(
    const float* __restrict__ v_seq,   // [B,S,2]
    const float* __restrict__ W_ih,    // [384,2]
    const float* __restrict__ W_hh,    // [384,128]
    const float* __restrict__ b_ih,    // [384]
    const float* __restrict__ b_hh)    // [384]
{
    extern __shared__ char smem[];
    uint4* AfragHi = (uint4*)(smem + OFF_A_HI);
    uint4* AfragLo = (uint4*)(smem + OFF_A_LO);
    uint32_t* hbh  = (uint32_t*)(smem + OFF_HB_HI);
    uint32_t* hbl  = (uint32_t*)(smem + OFF_HB_LO);
    u16* hbh16     = (u16*)(smem + OFF_HB_HI);
    u16* hbl16     = (u16*)(smem + OFF_HB_LO);
    float* Dbuf    = (float*)(smem + OFF_D);

    const int tid  = threadIdx.x;
    const int wid  = tid >> 5;
    const int lane = tid & 31;
    const int bglob = blockIdx.x * 8;

    // ---- Prologue: build A fragments (hi/lo bf16 splits of W_hh) ----
    for (int e = tid; e < 24 * 8 * 32; e += 768) {
        int mt = e >> 8, kt = (e >> 5) & 7, l = e & 31;
        int r0 = mt * 16 + (l >> 2);
        int c0 = kt * 16 + (l & 3) * 2;
        const float* Wr0 = W_hh + r0 * 128;
        const float* Wr1 = W_hh + (r0 + 8) * 128;
        float f[8] = { Wr0[c0], Wr0[c0 + 1], Wr1[c0], Wr1[c0 + 1],
                       Wr0[c0 + 8], Wr0[c0 + 9], Wr1[c0 + 8], Wr1[c0 + 9] };
        u16 hi[8], lo[8];
#pragma unroll
        for (int i = 0; i < 8; i++) bsplit(f[i], hi[i], lo[i]);
        uint4 ah, al;
        ah.x = (uint32_t)hi[0] | ((uint32_t)hi[1] << 16);
        ah.y = (uint32_t)hi[2] | ((uint32_t)hi[3] << 16);
        ah.z = (uint32_t)hi[4] | ((uint32_t)hi[5] << 16);
        ah.w = (uint32_t)hi[6] | ((uint32_t)hi[7] << 16);
        al.x = (uint32_t)lo[0] | ((uint32_t)lo[1] << 16);
        al.y = (uint32_t)lo[2] | ((uint32_t)lo[3] << 16);
        al.z = (uint32_t)lo[4] | ((uint32_t)lo[5] << 16);
        al.w = (uint32_t)lo[6] | ((uint32_t)lo[7] << 16);
        AfragHi[e] = ah;
        AfragLo[e] = al;
    }
    // zero h buffers (h0 = 0)
    for (int i = tid; i < 512; i += 768) { hbh[i] = 0u; hbl[i] = 0u; }

    // ---- Gate constants (threads 0..511: thread owns (j, batches bp, bp+4)) ----
    const int j  = tid & 127;
    const int bp = (tid >> 7) & 3;
    const float wr0 = W_ih[2 * j],               wr1 = W_ih[2 * j + 1];
    const float wz0 = W_ih[2 * (HID + j)],       wz1 = W_ih[2 * (HID + j) + 1];
    const float wn0 = W_ih[2 * (2 * HID + j)],   wn1 = W_ih[2 * (2 * HID + j) + 1];
    const float brt = b_ih[j] + b_hh[j];
    const float bzt = b_ih[HID + j] + b_hh[HID + j];
    const float bin_ = b_ih[2 * HID + j];
    const float bhn  = b_hh[2 * HID + j];

    // B fragment word index base for this lane
    const int bidx0 = (lane & 3) * 8 + (lane >> 2);   // + kt*64; b1 at +32
    // D write coords for this warp/lane
    const int drow = wid * 16 + (lane >> 2);
    const int dcol = (lane & 3) * 2;
    float* dst01 = Dbuf + drow * DSTRIDE + dcol;
    float* dst23 = Dbuf + (drow + 8) * DSTRIDE + dcol;
    // gate-side hB u16 indices
    const int hbi = ((j >> 1) * 8) * 2 + (j & 1);   // + b*2

    float hp[2] = {0.f, 0.f};
    __syncthreads();

    for (int s = 0; s < SEQ; ++s) {
        // prefetch v (gate threads) — in flight across the mma phase
        float2 vv[2];
        if (tid < 512) {
            vv[0] = *(const float2*)(v_seq + ((size_t)(bglob + bp) * SEQ + s) * 2);
            vv[1] = *(const float2*)(v_seq + ((size_t)(bglob + bp + 4) * SEQ + s) * 2);
        }

        // ---- MMA phase: all 24 warps ----
        float d0[4] = {0.f, 0.f, 0.f, 0.f};
        float d1[4] = {0.f, 0.f, 0.f, 0.f};
        const uint4* ah = AfragHi + wid * 256 + lane;
        const uint4* al = AfragLo + wid * 256 + lane;
#pragma unroll
        for (int kt = 0; kt < 8; kt++) {
            uint4 fh = ah[kt * 32];
            uint4 fl = al[kt * 32];
            int bi = kt * 64 + bidx0;
            uint32_t bh0 = hbh[bi], bh1 = hbh[bi + 32];
            uint32_t bl0 = hbl[bi], bl1 = hbl[bi + 32];
            float* dd = (kt & 1) ? d1 : d0;
            mma_bf16(dd, fh, bh0, bh1);
            mma_bf16(dd, fh, bl0, bl1);
            mma_bf16(dd, fl, bh0, bh1);
        }
        dst01[0] = d0[0] + d1[0];
        dst01[1] = d0[1] + d1[1];
        dst23[0] = d0[2] + d1[2];
        dst23[1] = d0[3] + d1[3];
        __syncthreads();

        // ---- Gate phase: threads 0..511 ----
        if (tid < 512) {
#pragma unroll
            for (int i = 0; i < 2; i++) {
                int b = bp + 4 * i;
                float gr = Dbuf[j * DSTRIDE + b];
                float gz = Dbuf[(128 + j) * DSTRIDE + b];
                float gn = Dbuf[(256 + j) * DSTRIDE + b];
                float2 v = vv[i];
                float r = fast_sigmoid(fmaf(wr0, v.x, fmaf(wr1, v.y, brt)) + gr);
                float z = fast_sigmoid(fmaf(wz0, v.x, fmaf(wz1, v.y, bzt)) + gz);
                float n = fast_tanh(fmaf(wn0, v.x, fmaf(wn1, v.y, bin_)) + r * (gn + bhn));
                float hnew = n + z * (hp[i] - n);
                hp[i] = hnew;
                g_hseq[((size_t)(bglob + b) * SEQ + s) * HID + j] = hnew;
                u16 hi, lo;
                bsplit(hnew, hi, lo);
                hbh16[hbi + b * 2] = hi;
                hbl16[hbi + b * 2] = lo;
            }
        }
        __syncthreads();
    }
}

// ---------------------------------------------------------------------------
// Epilogue pass 1: x_pred only. One warp per (b,s).
// ---------------------------------------------------------------------------
__global__ __launch_bounds__(256) void epi1_kernel(
    const float* __restrict__ W_out,   // [2,128]
    const float* __restrict__ b_out,   // [2]
    float* __restrict__ out)           // x_pred region: [B*S, 2]
{
    const int w    = (blockIdx.x * blockDim.x + threadIdx.x) >> 5;
    const int lane = threadIdx.x & 31;
    if (w >= BATCH * SEQ) return;

    const float4 w0 = *(const float4*)(W_out + lane * 4);
    const float4 w1 = *(const float4*)(W_out + HID + lane * 4);

    float4 hv = *(const float4*)(g_hseq + (size_t)w * HID + lane * 4);
    float xp0 = hv.x * w0.x + hv.y * w0.y + hv.z * w0.z + hv.w * w0.w;
    float xp1 = hv.x * w1.x + hv.y * w1.y + hv.z * w1.z + hv.w * w1.w;
#pragma unroll
    for (int o = 16; o; o >>= 1) {
        xp0 += __shfl_xor_sync(0xffffffffu, xp0, o);
        xp1 += __shfl_xor_sync(0xffffffffu, xp1, o);
    }
    if (lane == 0) {
        out[2 * (size_t)w]     = xp0 + b_out[0];
        out[2 * (size_t)w + 1] = xp1 + b_out[1];
    }
}

// ---------------------------------------------------------------------------
// Epilogue pass 2: violations. One thread per (b,s).
// ---------------------------------------------------------------------------
__global__ __launch_bounds__(256) void epi2_kernel(
    const float* __restrict__ x0,      // [B,2]
    const float* __restrict__ v_seq,   // [B,S,2]
    const float* __restrict__ W_r1,    // [64,4]
    const float* __restrict__ b_r1,    // [64]
    const float* __restrict__ W_r2,    // [2,64]
    const float* __restrict__ b_r2,    // [2]
    float* __restrict__ out)           // [2, B*S, 2]
{
    __shared__ float4 s_w1[64];
    __shared__ float  s_b1[64], s_w2a[64], s_w2b[64], s_b2[2];
    const int t = threadIdx.x;
    if (t < 64) {
        s_w1[t]  = *(const float4*)(W_r1 + t * 4);
        s_b1[t]  = b_r1[t];
        s_w2a[t] = W_r2[t];
        s_w2b[t] = W_r2[64 + t];
    }
    if (t < 2) s_b2[t] = b_r2[t];
    __syncthreads();

    const int idx = blockIdx.x * blockDim.x + t;
    if (idx >= BATCH * SEQ) return;
    const int b = idx >> 9;
    const int s = idx & 511;

    float xq0, xq1;
    if (s == 0) {
        xq0 = x0[2 * b];
        xq1 = x0[2 * b + 1];
    } else {
        xq0 = out[2 * (size_t)(idx - 1)];
        xq1 = out[2 * (size_t)(idx - 1) + 1];
    }
    const float xp0 = out[2 * (size_t)idx];
    const float xp1 = out[2 * (size_t)idx + 1];
    const float2 vv = *(const float2*)(v_seq + (size_t)idx * 2);

    float r0 = 0.0f, r1 = 0.0f;
#pragma unroll 8
    for (int m = 0; m < 64; m++) {
        float4 wq = s_w1[m];
        float h = fmaf(wq.x, xq0, fmaf(wq.y, xq1, fmaf(wq.z, vv.x, fmaf(wq.w, vv.y, s_b1[m]))));
        h = fmaxf(h, 0.0f);
        r0 = fmaf(h, s_w2a[m], r0);
        r1 = fmaf(h, s_w2b[m], r1);
    }
    const float pp0 = xq0 + vv.x + r0 + s_b2[0];
    const float pp1 = xq1 + vv.y + r1 + s_b2[1];

    const size_t off = (size_t)BATCH * SEQ * 2;
    out[off + 2 * (size_t)idx]     = xp0 - pp0;
    out[off + 2 * (size_t)idx + 1] = xp1 - pp1;
}

// ---------------------------------------------------------------------------
extern "C" void kernel_launch(void* const* d_in, const int* in_sizes, int n_in,
                              void* d_out, int out_size)
{
    const float* x0    = (const float*)d_in[0];
    const float* v_seq = (const float*)d_in[1];
    const float* W_ih  = (const float*)d_in[2];
    const float* W_hh  = (const float*)d_in[3];
    const float* b_ih  = (const float*)d_in[4];
    const float* b_hh  = (const float*)d_in[5];
    const float* W_out = (const float*)d_in[6];
    const float* b_out = (const float*)d_in[7];
    const float* W_r1  = (const float*)d_in[8];
    const float* b_r1  = (const float*)d_in[9];
    const float* W_r2  = (const float*)d_in[10];
    const float* b_r2  = (const float*)d_in[11];
    float* out = (float*)d_out;

    cudaFuncSetAttribute(gru_kernel, cudaFuncAttributeMaxDynamicSharedMemorySize, SMEM_BYTES);
    gru_kernel<<<BATCH / 8, 768, SMEM_BYTES>>>(v_seq, W_ih, W_hh, b_ih, b_hh);

    // pass 1: x_pred (one warp per (b,s))
    {
        const int total = BATCH * SEQ * 32;
        epi1_kernel<<<(total + 255) / 256, 256>>>(W_out, b_out, out);
    }
    // pass 2: violations (one thread per (b,s))
    {
        const int total = BATCH * SEQ;
        epi2_kernel<<<(total + 255) / 256, 256>>>(x0, v_seq, W_r1, b_r1, W_r2, b_r2, out);
    }
}